// round 13
// baseline (speedup 1.0000x reference)
#include <cuda_runtime.h>
#include <cuda_fp16.h>
#include <math.h>
#include <stdint.h>

#define SS   4096
#define DM   1024
#define HH   16
#define DKK  64
#define GG   1
#define NNG  (SS - 2*GG)     // 4094
#define KSEL 32
#define SCALE 0.125f         // 1/sqrt(64)
#define NSPL 16

// Scratch (device globals — no allocation allowed)
__device__ float  g_q[SS*DM];
__device__ float  g_k[SS*DM];
__device__ float  g_v[SS*DM];
__device__ __half g_oh[SS*DM];          // attention output, fp16 (A of out-GEMM)
__device__ __half g_hQ[SS*DM];
__device__ __half g_hK[SS*DM];
__device__ __half g_hV[SS*DM];
__device__ __half g_hWq[DM*DM];
__device__ __half g_hWk[DM*DM];
__device__ __half g_hWv[DM*DM];
__device__ __half g_hWo[DM*DM];
__device__ float  g_gpart[2*HH*NSPL*72];

// ---------------------------------------------------------------------------
// fp32 -> fp16 convert (vectorized), one launch per buffer.
// ---------------------------------------------------------------------------
__global__ void f2h(const float4* __restrict__ s, uint2* __restrict__ d, int n4) {
    int i = blockIdx.x * blockDim.x + threadIdx.x;
    if (i >= n4) return;
    float4 v = s[i];
    __half2 lo = __floats2half2_rn(v.x, v.y);
    __half2 hi = __floats2half2_rn(v.z, v.w);
    d[i] = make_uint2(*(uint32_t*)&lo, *(uint32_t*)&hi);
}

// ===========================================================================
// FP16 GEMM v4: CTA 128x256, BK=32 halves, 8 warps (2M x 4N), warp 64x64.
// fp16 operands in GMEM; cp.async 3-stage pipeline into swizzled smem;
// ldmatrix fragments; f32 accumulate. Layout identical to v3:
//  A smem: [128 m][32 k-halves], row stride 80B.
//  B smem: [32 k][256 n-halves], row stride 512B, chunk swizzle
//          p = (c & 24) | ((c&7) ^ (r&7)).
// grid.z selects one of up to 3 (A, B, C) triples.
// ===========================================================================
#define BM3 128
#define BN3 256
#define A_STRIDE 80
#define A_BUF    10240      // 128*80
#define B_OFF    30720      // 3*A_BUF
#define B_BUF    16384      // 32*512
#define GSMEM4   79872      // 3*A_BUF + 3*B_BUF
#define NSTAGE   3

__device__ __forceinline__ uint32_t smem_u32(const void* p) {
    uint32_t a;
    asm("{ .reg .u64 t; cvta.to.shared.u64 t, %1; cvt.u32.u64 %0, t; }"
        : "=r"(a) : "l"(p));
    return a;
}

#define CP16(dst, src) \
    asm volatile("cp.async.cg.shared.global [%0], [%1], 16;" :: "r"(dst), "l"(src))
#define CP_COMMIT() asm volatile("cp.async.commit_group;" ::: "memory")
#define CP_WAIT1()  asm volatile("cp.async.wait_group 1;" ::: "memory")
#define CP_WAIT0()  asm volatile("cp.async.wait_group 0;" ::: "memory")

#define LDM_X4(r, a) \
    asm volatile("ldmatrix.sync.aligned.m8n8.x4.shared.b16 {%0,%1,%2,%3}, [%4];" \
        : "=r"((r)[0]), "=r"((r)[1]), "=r"((r)[2]), "=r"((r)[3]) : "r"(a))
#define LDM_X4T(r, a) \
    asm volatile("ldmatrix.sync.aligned.m8n8.x4.trans.shared.b16 {%0,%1,%2,%3}, [%4];" \
        : "=r"((r)[0]), "=r"((r)[1]), "=r"((r)[2]), "=r"((r)[3]) : "r"(a))

__device__ __forceinline__ void mma_f16(float& c0, float& c1, float& c2, float& c3,
                                        uint32_t a0, uint32_t a1, uint32_t a2, uint32_t a3,
                                        uint32_t b0, uint32_t b1) {
    asm volatile(
        "mma.sync.aligned.m16n8k16.row.col.f32.f16.f16.f32 "
        "{%0,%1,%2,%3}, {%4,%5,%6,%7}, {%8,%9}, {%0,%1,%2,%3};"
        : "+f"(c0), "+f"(c1), "+f"(c2), "+f"(c3)
        : "r"(a0), "r"(a1), "r"(a2), "r"(a3), "r"(b0), "r"(b1));
}

__global__ __launch_bounds__(256, 1)
void gemm_f16(const __half* __restrict__ A0, const __half* __restrict__ A1,
              const __half* __restrict__ A2, const __half* __restrict__ B0,
              const __half* __restrict__ B1, const __half* __restrict__ B2,
              float* __restrict__ C0, float* __restrict__ C1,
              float* __restrict__ C2) {
    extern __shared__ char dsm[];
    const uint32_t sb = smem_u32(dsm);

    const int N = DM;
    const __half* A = (blockIdx.z == 0) ? A0 : (blockIdx.z == 1) ? A1 : A2;
    const __half* B = (blockIdx.z == 0) ? B0 : (blockIdx.z == 1) ? B1 : B2;
    float*        C = (blockIdx.z == 0) ? C0 : (blockIdx.z == 1) ? C1 : C2;

    const int tid  = threadIdx.x;
    const int lane = tid & 31;
    const int warp = tid >> 5;
    const int wm   = warp >> 2;       // 0..1
    const int wn   = warp & 3;        // 0..3
    const int gid  = lane >> 2;       // 0..7
    const int qid  = lane & 3;        // 0..3
    const int bx = blockIdx.x;        // N tile (256)
    const int by = blockIdx.y;        // M tile (128)

    // --- fill mappings ---
    const int am  = tid >> 1;
    const int acp = tid & 1;
    const __half* Ag = A + (size_t)(by * BM3 + am) * DM + acp * 16;
    const uint32_t aoffS = am * A_STRIDE + acp * 32;
    const int br  = tid >> 3;
    const int bcb = tid & 7;
    const __half* Bg = B + (size_t)br * DM + bx * BN3 + bcb * 8;
    uint32_t boffS[4];
#pragma unroll
    for (int jj = 0; jj < 4; jj++)
        boffS[jj] = br * 512 + (8 * jj + (bcb ^ (br & 7))) * 16;

    // --- ldmatrix lane bases ---
    const uint32_t aBase0 = (uint32_t)((wm * 64 + (lane & 7) + ((lane >> 3) & 1) * 8) * A_STRIDE
                                       + (lane >> 4) * 16);
    const uint32_t bBase0 = (uint32_t)(lane * 512 + wn * 128);
    const int lx = lane & 7;

    float acc[4][8][4];
#pragma unroll
    for (int mi = 0; mi < 4; mi++)
#pragma unroll
        for (int ni = 0; ni < 8; ni++)
#pragma unroll
            for (int r = 0; r < 4; r++) acc[mi][ni][r] = 0.0f;

    const int NITER = DM / 32;   // 32

    // issue one stage of cp.async fills
    auto issue = [&](int st) {
        const int k0 = st * 32;
        const int buf = st % NSTAGE;
        const uint32_t ab = sb + buf * A_BUF + aoffS;
        const __half* as = Ag + k0;
        CP16(ab, as);
        CP16(ab + 16, as + 8);
        const uint32_t bb = sb + B_OFF + buf * B_BUF;
        const __half* bs = Bg + (size_t)k0 * DM;
#pragma unroll
        for (int jj = 0; jj < 4; jj++)
            CP16(bb + boffS[jj], bs + jj * 64);
    };

    issue(0); CP_COMMIT();
    issue(1); CP_COMMIT();

    for (int it = 0; it < NITER; it++) {
        if (it + NSTAGE - 1 < NITER) {
            issue(it + NSTAGE - 1); CP_COMMIT();
            CP_WAIT1();
        } else {
            CP_WAIT0();
        }
        __syncthreads();

        const int cur = it % NSTAGE;
        const uint32_t aB = sb + cur * A_BUF + aBase0;
        const uint32_t bB = sb + B_OFF + cur * B_BUF + bBase0;
        uint32_t afr[8][4];
#pragma unroll
        for (int mi = 0; mi < 4; mi++) {
            LDM_X4(afr[mi * 2 + 0], aB + mi * (16 * A_STRIDE) + 0);
            LDM_X4(afr[mi * 2 + 1], aB + mi * (16 * A_STRIDE) + 32);
        }
        uint32_t bfr[8][4];
#pragma unroll
        for (int ni = 0; ni < 8; ni++)
            LDM_X4T(bfr[ni], bB + ((ni ^ lx) << 4));

#pragma unroll
        for (int kc = 0; kc < 2; kc++)
#pragma unroll
            for (int mi = 0; mi < 4; mi++)
#pragma unroll
                for (int ni = 0; ni < 8; ni++)
                    mma_f16(acc[mi][ni][0], acc[mi][ni][1], acc[mi][ni][2], acc[mi][ni][3],
                            afr[mi * 2 + kc][0], afr[mi * 2 + kc][1],
                            afr[mi * 2 + kc][2], afr[mi * 2 + kc][3],
                            bfr[ni][2 * kc], bfr[ni][2 * kc + 1]);

        __syncthreads();
    }

    // epilogue
#pragma unroll
    for (int mi = 0; mi < 4; mi++) {
        const int row = by * BM3 + wm * 64 + mi * 16 + gid;
#pragma unroll
        for (int ni = 0; ni < 8; ni++) {
            const int col = bx * BN3 + wn * 64 + ni * 8 + 2 * qid;
            *(float2*)(C + (size_t)row * N + col) =
                make_float2(acc[mi][ni][0], acc[mi][ni][1]);
            *(float2*)(C + (size_t)(row + 8) * N + col) =
                make_float2(acc[mi][ni][2], acc[mi][ni][3]);
        }
    }
}

// ---------------------------------------------------------------------------
// Sparse attention: CTA = 64 tokens x 1 head, smem K/V cache; idx decoded
// inline. Output stored fp16 to g_oh.
// ---------------------------------------------------------------------------
#define TB      64
#define CROWS   96
#define CSLOTS  97
#define CSTRIDE 68

__global__ __launch_bounds__(256)
void sparse_attn(const void* __restrict__ idxraw) {
    __shared__ float Kc[CSLOTS * CSTRIDE];
    __shared__ float Vc[CSLOTS * CSTRIDE];
    __shared__ float qsm[8][CSTRIDE];

    const int b    = blockIdx.x;
    const int h    = blockIdx.y;
    const int tid  = threadIdx.x;
    const int lane = tid & 31;
    const int w    = tid >> 5;

    const int* p32 = (const int*)idxraw;
    const bool is64 = (p32[1] == 0);

    int rowbase = b * TB - 10;
    if (rowbase < 0) rowbase = 0;
    if (rowbase > SS - CROWS) rowbase = SS - CROWS;

    for (int i = tid; i < CSLOTS * 16; i += 256) {
        const int r  = i >> 4;
        const int c4 = (i & 15) * 4;
        const int src = (r < CROWS) ? (rowbase + r) : 0;
        const float4 kv = *(const float4*)(g_k + (size_t)src * DM + h * DKK + c4);
        const float4 vv = *(const float4*)(g_v + (size_t)src * DM + h * DKK + c4);
        *(float4*)(Kc + r * CSTRIDE + c4) = kv;
        *(float4*)(Vc + r * CSTRIDE + c4) = vv;
    }
    __syncthreads();

    for (int i = 0; i < 8; i++) {
        const int t = b * TB + w * 8 + i;
        if (t >= NNG) break;

        __syncwarp();
        *(float2*)(&qsm[w][2 * lane]) =
            *(const float2*)(g_q + (size_t)(t + GG) * DM + h * DKK + 2 * lane);
        __syncwarp();

        const int kidx = is64 ? (int)((const long long*)idxraw)[t * KSEL + lane]
                              : p32[t * KSEL + lane];
        int slot = kidx - rowbase;
        if (kidx == 0) slot = CROWS;
        else if (slot < 0 || slot >= CROWS) slot = -1;

        float dot = 0.0f;
        if (slot >= 0) {
            const float* kr = Kc + slot * CSTRIDE;
            const int rot = slot & 31;
#pragma unroll
            for (int pp = 0; pp < 32; pp++) {
                const int p = (pp + rot) & 31;
                const float2 kv = *(const float2*)(kr + 2 * p);
                const float2 qv = *(const float2*)(&qsm[w][2 * p]);
                dot += kv.x * qv.x + kv.y * qv.y;
            }
        } else {
            const float* kr = g_k + (size_t)kidx * DM + h * DKK;
            const int rot = lane;
#pragma unroll
            for (int pp = 0; pp < 32; pp++) {
                const int p = (pp + rot) & 31;
                const float2 kv = *(const float2*)(kr + 2 * p);
                const float2 qv = *(const float2*)(&qsm[w][2 * p]);
                dot += kv.x * qv.x + kv.y * qv.y;
            }
        }
        const float lg = dot * SCALE;

        float m = lg;
#pragma unroll
        for (int o = 16; o; o >>= 1) m = fmaxf(m, __shfl_xor_sync(0xffffffffu, m, o));
        const float e = __expf(lg - m);
        float sum = e;
#pragma unroll
        for (int o = 16; o; o >>= 1) sum += __shfl_xor_sync(0xffffffffu, sum, o);
        const float prob = e / sum;

        float acc0 = 0.0f, acc1 = 0.0f;
#pragma unroll
        for (int j = 0; j < 32; j++) {
            const float pj = __shfl_sync(0xffffffffu, prob, j);
            const int   sj = __shfl_sync(0xffffffffu, slot, j);
            const int   kj = __shfl_sync(0xffffffffu, kidx, j);
            if (sj >= 0) {
                acc0 = fmaf(pj, Vc[sj * CSTRIDE + lane],      acc0);
                acc1 = fmaf(pj, Vc[sj * CSTRIDE + lane + 32], acc1);
            } else {
                const float* vr = g_v + (size_t)kj * DM + h * DKK;
                acc0 = fmaf(pj, vr[lane],      acc0);
                acc1 = fmaf(pj, vr[lane + 32], acc1);
            }
        }
        __half* orow = g_oh + (size_t)(t + GG) * DM + h * DKK;
        orow[lane]      = __float2half(acc0);
        orow[lane + 32] = __float2half(acc1);
    }
}

// ---------------------------------------------------------------------------
// Global attention, split-K x16: grid (16, 16 heads, 2 tokens), 256 keys/blk.
// ---------------------------------------------------------------------------
__global__ __launch_bounds__(256)
void global_attn_split() {
    __shared__ float lg[256];
    __shared__ float red[256];
    __shared__ float ored[4][DKK];
    __shared__ __align__(16) float qs[DKK];

    const int spl = blockIdx.x;
    const int h   = blockIdx.y;
    const int gi  = blockIdx.z;
    const int srow = gi ? (SS - 1) : 0;
    const int tid = threadIdx.x;
    const int n0  = spl * 256;

    if (tid < DKK) qs[tid] = g_q[(size_t)srow * DM + h * DKK + tid];
    __syncthreads();

    {
        const int n = n0 + tid;
        const float4* kr = (const float4*)(g_k + (size_t)n * DM + h * DKK);
        const float4* qr = (const float4*)qs;
        float dot = 0.0f;
#pragma unroll
        for (int i = 0; i < 16; i++) {
            float4 kv = kr[i], qv = qr[i];
            dot = fmaf(kv.x, qv.x, dot);
            dot = fmaf(kv.y, qv.y, dot);
            dot = fmaf(kv.z, qv.z, dot);
            dot = fmaf(kv.w, qv.w, dot);
        }
        lg[tid] = dot * SCALE;
    }
    red[tid] = lg[tid]; __syncthreads();
    for (int st = 128; st; st >>= 1) {
        if (tid < st) red[tid] = fmaxf(red[tid], red[tid + st]);
        __syncthreads();
    }
    const float m = red[0];
    __syncthreads();

    const float e = __expf(lg[tid] - m);
    lg[tid] = e;
    red[tid] = e; __syncthreads();
    for (int st = 128; st; st >>= 1) {
        if (tid < st) red[tid] += red[tid + st];
        __syncthreads();
    }
    const float s = red[0];
    __syncthreads();

    const int d = tid & 63;
    const int c = tid >> 6;
    float acc = 0.0f;
    const float* vb = g_v + h * DKK + d;
    const int na = c * 64, nb = na + 64;
    for (int nl = na; nl < nb; nl++)
        acc = fmaf(lg[nl], vb[(size_t)(n0 + nl) * DM], acc);
    ored[c][d] = acc;
    __syncthreads();

    const int base = ((gi * HH + h) * NSPL + spl) * 72;
    if (tid < DKK)
        g_gpart[base + tid] = ored[0][tid] + ored[1][tid] + ored[2][tid] + ored[3][tid];
    else if (tid == 64) g_gpart[base + 64] = m;
    else if (tid == 65) g_gpart[base + 65] = s;
}

__global__ __launch_bounds__(64)
void global_attn_combine() {
    const int blk = blockIdx.x;
    const int d   = threadIdx.x;
    const int gi  = blk >> 4;
    const int h   = blk & 15;
    const int srow = gi ? (SS - 1) : 0;

    float M = -1e30f;
#pragma unroll
    for (int i = 0; i < NSPL; i++)
        M = fmaxf(M, g_gpart[(blk * NSPL + i) * 72 + 64]);
    float S = 0.0f, acc = 0.0f;
#pragma unroll
    for (int i = 0; i < NSPL; i++) {
        const int base = (blk * NSPL + i) * 72;
        const float wgt = __expf(g_gpart[base + 64] - M);
        S   += g_gpart[base + 65] * wgt;
        acc += g_gpart[base + d] * wgt;
    }
    g_oh[(size_t)srow * DM + h * DKK + d] = __float2half(acc / S);
}

// ---------------------------------------------------------------------------
extern "C" void kernel_launch(void* const* d_in, const int* in_sizes, int n_in,
                              void* d_out, int out_size) {
    const float* Q  = (const float*)d_in[0];
    const float* Kk = (const float*)d_in[1];
    const float* V  = (const float*)d_in[2];
    const float* Wq = (const float*)d_in[3];
    const float* Wk = (const float*)d_in[4];
    const float* Wv = (const float*)d_in[5];
    const float* Wo = (const float*)d_in[6];
    const void*  idx = (const void*)d_in[7];
    float* out = (float*)d_out;

    float *pq, *pk, *pv;
    __half *hQ, *hK, *hV, *hWq, *hWk, *hWv, *hWo, *oh;
    cudaGetSymbolAddress((void**)&pq,  g_q);
    cudaGetSymbolAddress((void**)&pk,  g_k);
    cudaGetSymbolAddress((void**)&pv,  g_v);
    cudaGetSymbolAddress((void**)&hQ,  g_hQ);
    cudaGetSymbolAddress((void**)&hK,  g_hK);
    cudaGetSymbolAddress((void**)&hV,  g_hV);
    cudaGetSymbolAddress((void**)&hWq, g_hWq);
    cudaGetSymbolAddress((void**)&hWk, g_hWk);
    cudaGetSymbolAddress((void**)&hWv, g_hWv);
    cudaGetSymbolAddress((void**)&hWo, g_hWo);
    cudaGetSymbolAddress((void**)&oh,  g_oh);

    cudaFuncSetAttribute(gemm_f16, cudaFuncAttributeMaxDynamicSharedMemorySize, GSMEM4);

    // fp32 -> fp16 copies of activations + weights
    const int NA4 = SS * DM / 4;   // 1M
    const int NW4 = DM * DM / 4;   // 256K
    f2h<<<NA4 / 256, 256>>>((const float4*)Q,  (uint2*)hQ,  NA4);
    f2h<<<NA4 / 256, 256>>>((const float4*)Kk, (uint2*)hK,  NA4);
    f2h<<<NA4 / 256, 256>>>((const float4*)V,  (uint2*)hV,  NA4);
    f2h<<<NW4 / 256, 256>>>((const float4*)Wq, (uint2*)hWq, NW4);
    f2h<<<NW4 / 256, 256>>>((const float4*)Wk, (uint2*)hWk, NW4);
    f2h<<<NW4 / 256, 256>>>((const float4*)Wv, (uint2*)hWv, NW4);
    f2h<<<NW4 / 256, 256>>>((const float4*)Wo, (uint2*)hWo, NW4);

    dim3 qkv_grid(DM / BN3, SS / BM3, 3);   // (4, 32, 3)
    gemm_f16<<<qkv_grid, 256, GSMEM4>>>(hQ, hK, hV, hWq, hWk, hWv, pq, pk, pv);

    dim3 sp_grid((NNG + TB - 1) / TB, HH);  // (64, 16)
    sparse_attn<<<sp_grid, 256>>>(idx);

    dim3 gs_grid(NSPL, HH, 2);
    global_attn_split<<<gs_grid, 256>>>();
    global_attn_combine<<<2 * HH, 64>>>();

    dim3 o_grid(DM / BN3, SS / BM3, 1);     // (4, 32, 1)
    gemm_f16<<<o_grid, 256, GSMEM4>>>(oh, oh, oh, hWo, hWo, hWo, out, out, out);
}

// round 14
// speedup vs baseline: 1.5661x; 1.5661x over previous
#include <cuda_runtime.h>
#include <cuda_fp16.h>
#include <math.h>
#include <stdint.h>

#define SS   4096
#define DM   1024
#define HH   16
#define DKK  64
#define GG   1
#define NNG  (SS - 2*GG)     // 4094
#define KSEL 32
#define SCALE 0.125f         // 1/sqrt(64)
#define NSPL 16

// Scratch (device globals — no allocation allowed)
__device__ float  g_q[SS*DM];
__device__ float  g_k[SS*DM];
__device__ float  g_v[SS*DM];
__device__ __half g_oh[SS*DM];          // attention output, fp16 (A of out-GEMM)
__device__ __half g_hQ[SS*DM];
__device__ __half g_hK[SS*DM];
__device__ __half g_hV[SS*DM];
__device__ __half g_hWq[DM*DM];
__device__ __half g_hWk[DM*DM];
__device__ __half g_hWv[DM*DM];
__device__ __half g_hWo[DM*DM];
__device__ float  g_gpart[2*HH*NSPL*72];

// ---------------------------------------------------------------------------
// Fused fp32 -> fp16 convert for all 7 buffers in one launch.
// blockIdx.y selects buffer; activations need 1M float4s, weights 256K.
// ---------------------------------------------------------------------------
__global__ void f2h_all(const float4* __restrict__ Q,  const float4* __restrict__ K,
                        const float4* __restrict__ V,  const float4* __restrict__ Wq,
                        const float4* __restrict__ Wk, const float4* __restrict__ Wv,
                        const float4* __restrict__ Wo) {
    const int z = blockIdx.y;
    const int i = blockIdx.x * blockDim.x + threadIdx.x;
    const float4* s;
    uint2* d;
    int n4;
    switch (z) {
        case 0: s = Q;  d = (uint2*)g_hQ;  n4 = SS*DM/4; break;
        case 1: s = K;  d = (uint2*)g_hK;  n4 = SS*DM/4; break;
        case 2: s = V;  d = (uint2*)g_hV;  n4 = SS*DM/4; break;
        case 3: s = Wq; d = (uint2*)g_hWq; n4 = DM*DM/4; break;
        case 4: s = Wk; d = (uint2*)g_hWk; n4 = DM*DM/4; break;
        case 5: s = Wv; d = (uint2*)g_hWv; n4 = DM*DM/4; break;
        default: s = Wo; d = (uint2*)g_hWo; n4 = DM*DM/4; break;
    }
    if (i >= n4) return;
    float4 v = s[i];
    __half2 lo = __floats2half2_rn(v.x, v.y);
    __half2 hi = __floats2half2_rn(v.z, v.w);
    d[i] = make_uint2(*(uint32_t*)&lo, *(uint32_t*)&hi);
}

// ===========================================================================
// FP16 GEMM v5 = R12 pipeline + fp16 GMEM operands (no in-loop conversion).
// CTA 128x256, BK=32 halves, 8 warps (2M x 4N), warp 64x64, f32 accumulate.
//  A smem: [128 m][32 k-halves], row stride 80B.
//  B smem: [32 k][256 n-halves], row stride 512B, chunk swizzle
//          p = (c & 24) | ((c&7) ^ (r&7)); ldmatrix.x4.trans.
// Double-buffered, register-staged prefetch, ONE __syncthreads per iter.
// grid.z selects one of up to 3 (A, B, C) triples.
// ===========================================================================
#define BM3 128
#define BN3 256
#define A_STRIDE 80
#define A_BUF    10240      // 128*80
#define B_OFF    20480      // 2*A_BUF
#define B_BUF    16384      // 32*512
#define GSMEM5   53248      // 2*A_BUF + 2*B_BUF

__device__ __forceinline__ uint32_t smem_u32(const void* p) {
    uint32_t a;
    asm("{ .reg .u64 t; cvta.to.shared.u64 t, %1; cvt.u32.u64 %0, t; }"
        : "=r"(a) : "l"(p));
    return a;
}

#define LDM_X4(r, a) \
    asm volatile("ldmatrix.sync.aligned.m8n8.x4.shared.b16 {%0,%1,%2,%3}, [%4];" \
        : "=r"((r)[0]), "=r"((r)[1]), "=r"((r)[2]), "=r"((r)[3]) : "r"(a))
#define LDM_X4T(r, a) \
    asm volatile("ldmatrix.sync.aligned.m8n8.x4.trans.shared.b16 {%0,%1,%2,%3}, [%4];" \
        : "=r"((r)[0]), "=r"((r)[1]), "=r"((r)[2]), "=r"((r)[3]) : "r"(a))

__device__ __forceinline__ void mma_f16(float& c0, float& c1, float& c2, float& c3,
                                        uint32_t a0, uint32_t a1, uint32_t a2, uint32_t a3,
                                        uint32_t b0, uint32_t b1) {
    asm volatile(
        "mma.sync.aligned.m16n8k16.row.col.f32.f16.f16.f32 "
        "{%0,%1,%2,%3}, {%4,%5,%6,%7}, {%8,%9}, {%0,%1,%2,%3};"
        : "+f"(c0), "+f"(c1), "+f"(c2), "+f"(c3)
        : "r"(a0), "r"(a1), "r"(a2), "r"(a3), "r"(b0), "r"(b1));
}

__global__ __launch_bounds__(256, 1)
void gemm_f16(const __half* __restrict__ A0, const __half* __restrict__ A1,
              const __half* __restrict__ A2, const __half* __restrict__ B0,
              const __half* __restrict__ B1, const __half* __restrict__ B2,
              float* __restrict__ C0, float* __restrict__ C1,
              float* __restrict__ C2) {
    extern __shared__ char dsm[];
    const uint32_t sb = smem_u32(dsm);

    const int N = DM;
    const __half* A = (blockIdx.z == 0) ? A0 : (blockIdx.z == 1) ? A1 : A2;
    const __half* B = (blockIdx.z == 0) ? B0 : (blockIdx.z == 1) ? B1 : B2;
    float*        C = (blockIdx.z == 0) ? C0 : (blockIdx.z == 1) ? C1 : C2;

    const int tid  = threadIdx.x;
    const int lane = tid & 31;
    const int warp = tid >> 5;
    const int wm   = warp >> 2;       // 0..1
    const int wn   = warp & 3;        // 0..3
    const int gid  = lane >> 2;       // 0..7
    const int qid  = lane & 3;        // 0..3
    const int bx = blockIdx.x;        // N tile (256)
    const int by = blockIdx.y;        // M tile (128)

    // --- fill mappings ---
    // A: thread -> m = tid>>1, cp = tid&1 (16 halves = 32B each): 2 LDG.128 + 2 STS.128
    const int am  = tid >> 1;
    const int acp = tid & 1;
    const __half* Ag = A + (size_t)(by * BM3 + am) * DM + acp * 16;
    const uint32_t aoffS = am * A_STRIDE + acp * 32;
    // B: thread -> k-row r = tid>>3, chunk col cb = tid&7: 4 LDG.128 + 4 STS.128
    const int br  = tid >> 3;
    const int bcb = tid & 7;
    const __half* Bg = B + (size_t)br * DM + bx * BN3 + bcb * 8;
    uint32_t boffS[4];
#pragma unroll
    for (int jj = 0; jj < 4; jj++)
        boffS[jj] = br * 512 + (8 * jj + (bcb ^ (br & 7))) * 16;

    // --- ldmatrix lane bases ---
    const uint32_t aBase0 = (uint32_t)((wm * 64 + (lane & 7) + ((lane >> 3) & 1) * 8) * A_STRIDE
                                       + (lane >> 4) * 16);
    const uint32_t bBase0 = (uint32_t)(lane * 512 + wn * 128);
    const int lx = lane & 7;

    float acc[4][8][4];
#pragma unroll
    for (int mi = 0; mi < 4; mi++)
#pragma unroll
        for (int ni = 0; ni < 8; ni++)
#pragma unroll
            for (int r = 0; r < 4; r++) acc[mi][ni][r] = 0.0f;

    uint4 pa[2], pb[4];

    // ---- prologue: stage 0 ----
    pa[0] = *(const uint4*)(Ag);
    pa[1] = *(const uint4*)(Ag + 8);
#pragma unroll
    for (int jj = 0; jj < 4; jj++) pb[jj] = *(const uint4*)(Bg + jj * 64);
    {
        *(uint4*)(dsm + aoffS)      = pa[0];
        *(uint4*)(dsm + aoffS + 16) = pa[1];
#pragma unroll
        for (int jj = 0; jj < 4; jj++)
            *(uint4*)(dsm + B_OFF + boffS[jj]) = pb[jj];
    }
    __syncthreads();

    const int NITER = DM / 32;   // 32
    for (int it = 0; it < NITER; it++) {
        const int cur = it & 1;

        // prefetch next stage into registers
        if (it + 1 < NITER) {
            const int k0 = (it + 1) * 32;
            pa[0] = *(const uint4*)(Ag + k0);
            pa[1] = *(const uint4*)(Ag + k0 + 8);
            const __half* Bg2 = Bg + (size_t)k0 * DM;
#pragma unroll
            for (int jj = 0; jj < 4; jj++) pb[jj] = *(const uint4*)(Bg2 + jj * 64);
        }

        // fragments
        const uint32_t aB = sb + cur * A_BUF + aBase0;
        const uint32_t bB = sb + B_OFF + cur * B_BUF + bBase0;
        uint32_t afr[8][4];
#pragma unroll
        for (int mi = 0; mi < 4; mi++) {
            LDM_X4(afr[mi * 2 + 0], aB + mi * (16 * A_STRIDE) + 0);
            LDM_X4(afr[mi * 2 + 1], aB + mi * (16 * A_STRIDE) + 32);
        }
        uint32_t bfr[8][4];
#pragma unroll
        for (int ni = 0; ni < 8; ni++)
            LDM_X4T(bfr[ni], bB + ((ni ^ lx) << 4));

        // MMAs
#pragma unroll
        for (int kc = 0; kc < 2; kc++)
#pragma unroll
            for (int mi = 0; mi < 4; mi++)
#pragma unroll
                for (int ni = 0; ni < 8; ni++)
                    mma_f16(acc[mi][ni][0], acc[mi][ni][1], acc[mi][ni][2], acc[mi][ni][3],
                            afr[mi * 2 + kc][0], afr[mi * 2 + kc][1],
                            afr[mi * 2 + kc][2], afr[mi * 2 + kc][3],
                            bfr[ni][2 * kc], bfr[ni][2 * kc + 1]);

        // store prefetched stage
        if (it + 1 < NITER) {
            const int nxt = (it + 1) & 1;
            char* ab = dsm + nxt * A_BUF + aoffS;
            *(uint4*)(ab)      = pa[0];
            *(uint4*)(ab + 16) = pa[1];
            char* bb = dsm + B_OFF + nxt * B_BUF;
#pragma unroll
            for (int jj = 0; jj < 4; jj++)
                *(uint4*)(bb + boffS[jj]) = pb[jj];
        }
        __syncthreads();
    }

    // epilogue
#pragma unroll
    for (int mi = 0; mi < 4; mi++) {
        const int row = by * BM3 + wm * 64 + mi * 16 + gid;
#pragma unroll
        for (int ni = 0; ni < 8; ni++) {
            const int col = bx * BN3 + wn * 64 + ni * 8 + 2 * qid;
            *(float2*)(C + (size_t)row * N + col) =
                make_float2(acc[mi][ni][0], acc[mi][ni][1]);
            *(float2*)(C + (size_t)(row + 8) * N + col) =
                make_float2(acc[mi][ni][2], acc[mi][ni][3]);
        }
    }
}

// ---------------------------------------------------------------------------
// Sparse attention: CTA = 64 tokens x 1 head, smem K/V cache; idx decoded
// inline. Output stored fp16 to g_oh.
// ---------------------------------------------------------------------------
#define TB      64
#define CROWS   96
#define CSLOTS  97
#define CSTRIDE 68

__global__ __launch_bounds__(256)
void sparse_attn(const void* __restrict__ idxraw) {
    __shared__ float Kc[CSLOTS * CSTRIDE];
    __shared__ float Vc[CSLOTS * CSTRIDE];
    __shared__ float qsm[8][CSTRIDE];

    const int b    = blockIdx.x;
    const int h    = blockIdx.y;
    const int tid  = threadIdx.x;
    const int lane = tid & 31;
    const int w    = tid >> 5;

    const int* p32 = (const int*)idxraw;
    const bool is64 = (p32[1] == 0);

    int rowbase = b * TB - 10;
    if (rowbase < 0) rowbase = 0;
    if (rowbase > SS - CROWS) rowbase = SS - CROWS;

    for (int i = tid; i < CSLOTS * 16; i += 256) {
        const int r  = i >> 4;
        const int c4 = (i & 15) * 4;
        const int src = (r < CROWS) ? (rowbase + r) : 0;
        const float4 kv = *(const float4*)(g_k + (size_t)src * DM + h * DKK + c4);
        const float4 vv = *(const float4*)(g_v + (size_t)src * DM + h * DKK + c4);
        *(float4*)(Kc + r * CSTRIDE + c4) = kv;
        *(float4*)(Vc + r * CSTRIDE + c4) = vv;
    }
    __syncthreads();

    for (int i = 0; i < 8; i++) {
        const int t = b * TB + w * 8 + i;
        if (t >= NNG) break;

        __syncwarp();
        *(float2*)(&qsm[w][2 * lane]) =
            *(const float2*)(g_q + (size_t)(t + GG) * DM + h * DKK + 2 * lane);
        __syncwarp();

        const int kidx = is64 ? (int)((const long long*)idxraw)[t * KSEL + lane]
                              : p32[t * KSEL + lane];
        int slot = kidx - rowbase;
        if (kidx == 0) slot = CROWS;
        else if (slot < 0 || slot >= CROWS) slot = -1;

        float dot = 0.0f;
        if (slot >= 0) {
            const float* kr = Kc + slot * CSTRIDE;
            const int rot = slot & 31;
#pragma unroll
            for (int pp = 0; pp < 32; pp++) {
                const int p = (pp + rot) & 31;
                const float2 kv = *(const float2*)(kr + 2 * p);
                const float2 qv = *(const float2*)(&qsm[w][2 * p]);
                dot += kv.x * qv.x + kv.y * qv.y;
            }
        } else {
            const float* kr = g_k + (size_t)kidx * DM + h * DKK;
            const int rot = lane;
#pragma unroll
            for (int pp = 0; pp < 32; pp++) {
                const int p = (pp + rot) & 31;
                const float2 kv = *(const float2*)(kr + 2 * p);
                const float2 qv = *(const float2*)(&qsm[w][2 * p]);
                dot += kv.x * qv.x + kv.y * qv.y;
            }
        }
        const float lg = dot * SCALE;

        float m = lg;
#pragma unroll
        for (int o = 16; o; o >>= 1) m = fmaxf(m, __shfl_xor_sync(0xffffffffu, m, o));
        const float e = __expf(lg - m);
        float sum = e;
#pragma unroll
        for (int o = 16; o; o >>= 1) sum += __shfl_xor_sync(0xffffffffu, sum, o);
        const float prob = e / sum;

        float acc0 = 0.0f, acc1 = 0.0f;
#pragma unroll
        for (int j = 0; j < 32; j++) {
            const float pj = __shfl_sync(0xffffffffu, prob, j);
            const int   sj = __shfl_sync(0xffffffffu, slot, j);
            const int   kj = __shfl_sync(0xffffffffu, kidx, j);
            if (sj >= 0) {
                acc0 = fmaf(pj, Vc[sj * CSTRIDE + lane],      acc0);
                acc1 = fmaf(pj, Vc[sj * CSTRIDE + lane + 32], acc1);
            } else {
                const float* vr = g_v + (size_t)kj * DM + h * DKK;
                acc0 = fmaf(pj, vr[lane],      acc0);
                acc1 = fmaf(pj, vr[lane + 32], acc1);
            }
        }
        __half* orow = g_oh + (size_t)(t + GG) * DM + h * DKK;
        orow[lane]      = __float2half(acc0);
        orow[lane + 32] = __float2half(acc1);
    }
}

// ---------------------------------------------------------------------------
// Global attention, split-K x16: grid (16, 16 heads, 2 tokens), 256 keys/blk.
// ---------------------------------------------------------------------------
__global__ __launch_bounds__(256)
void global_attn_split() {
    __shared__ float lg[256];
    __shared__ float red[256];
    __shared__ float ored[4][DKK];
    __shared__ __align__(16) float qs[DKK];

    const int spl = blockIdx.x;
    const int h   = blockIdx.y;
    const int gi  = blockIdx.z;
    const int srow = gi ? (SS - 1) : 0;
    const int tid = threadIdx.x;
    const int n0  = spl * 256;

    if (tid < DKK) qs[tid] = g_q[(size_t)srow * DM + h * DKK + tid];
    __syncthreads();

    {
        const int n = n0 + tid;
        const float4* kr = (const float4*)(g_k + (size_t)n * DM + h * DKK);
        const float4* qr = (const float4*)qs;
        float dot = 0.0f;
#pragma unroll
        for (int i = 0; i < 16; i++) {
            float4 kv = kr[i], qv = qr[i];
            dot = fmaf(kv.x, qv.x, dot);
            dot = fmaf(kv.y, qv.y, dot);
            dot = fmaf(kv.z, qv.z, dot);
            dot = fmaf(kv.w, qv.w, dot);
        }
        lg[tid] = dot * SCALE;
    }
    red[tid] = lg[tid]; __syncthreads();
    for (int st = 128; st; st >>= 1) {
        if (tid < st) red[tid] = fmaxf(red[tid], red[tid + st]);
        __syncthreads();
    }
    const float m = red[0];
    __syncthreads();

    const float e = __expf(lg[tid] - m);
    lg[tid] = e;
    red[tid] = e; __syncthreads();
    for (int st = 128; st; st >>= 1) {
        if (tid < st) red[tid] += red[tid + st];
        __syncthreads();
    }
    const float s = red[0];
    __syncthreads();

    const int d = tid & 63;
    const int c = tid >> 6;
    float acc = 0.0f;
    const float* vb = g_v + h * DKK + d;
    const int na = c * 64, nb = na + 64;
    for (int nl = na; nl < nb; nl++)
        acc = fmaf(lg[nl], vb[(size_t)(n0 + nl) * DM], acc);
    ored[c][d] = acc;
    __syncthreads();

    const int base = ((gi * HH + h) * NSPL + spl) * 72;
    if (tid < DKK)
        g_gpart[base + tid] = ored[0][tid] + ored[1][tid] + ored[2][tid] + ored[3][tid];
    else if (tid == 64) g_gpart[base + 64] = m;
    else if (tid == 65) g_gpart[base + 65] = s;
}

__global__ __launch_bounds__(64)
void global_attn_combine() {
    const int blk = blockIdx.x;
    const int d   = threadIdx.x;
    const int gi  = blk >> 4;
    const int h   = blk & 15;
    const int srow = gi ? (SS - 1) : 0;

    float M = -1e30f;
#pragma unroll
    for (int i = 0; i < NSPL; i++)
        M = fmaxf(M, g_gpart[(blk * NSPL + i) * 72 + 64]);
    float S = 0.0f, acc = 0.0f;
#pragma unroll
    for (int i = 0; i < NSPL; i++) {
        const int base = (blk * NSPL + i) * 72;
        const float wgt = __expf(g_gpart[base + 64] - M);
        S   += g_gpart[base + 65] * wgt;
        acc += g_gpart[base + d] * wgt;
    }
    g_oh[(size_t)srow * DM + h * DKK + d] = __float2half(acc / S);
}

// ---------------------------------------------------------------------------
extern "C" void kernel_launch(void* const* d_in, const int* in_sizes, int n_in,
                              void* d_out, int out_size) {
    const float* Q  = (const float*)d_in[0];
    const float* Kk = (const float*)d_in[1];
    const float* V  = (const float*)d_in[2];
    const float* Wq = (const float*)d_in[3];
    const float* Wk = (const float*)d_in[4];
    const float* Wv = (const float*)d_in[5];
    const float* Wo = (const float*)d_in[6];
    const void*  idx = (const void*)d_in[7];
    float* out = (float*)d_out;

    float *pq, *pk, *pv;
    __half *hQ, *hK, *hV, *hWq, *hWk, *hWv, *hWo, *oh;
    cudaGetSymbolAddress((void**)&pq,  g_q);
    cudaGetSymbolAddress((void**)&pk,  g_k);
    cudaGetSymbolAddress((void**)&pv,  g_v);
    cudaGetSymbolAddress((void**)&hQ,  g_hQ);
    cudaGetSymbolAddress((void**)&hK,  g_hK);
    cudaGetSymbolAddress((void**)&hV,  g_hV);
    cudaGetSymbolAddress((void**)&hWq, g_hWq);
    cudaGetSymbolAddress((void**)&hWk, g_hWk);
    cudaGetSymbolAddress((void**)&hWv, g_hWv);
    cudaGetSymbolAddress((void**)&hWo, g_hWo);
    cudaGetSymbolAddress((void**)&oh,  g_oh);

    cudaFuncSetAttribute(gemm_f16, cudaFuncAttributeMaxDynamicSharedMemorySize, GSMEM5);

    // fused fp32 -> fp16 conversion (activations + weights), single launch
    dim3 cg(SS * DM / 4 / 256, 7);
    f2h_all<<<cg, 256>>>((const float4*)Q,  (const float4*)Kk, (const float4*)V,
                         (const float4*)Wq, (const float4*)Wk, (const float4*)Wv,
                         (const float4*)Wo);

    dim3 qkv_grid(DM / BN3, SS / BM3, 3);   // (4, 32, 3)
    gemm_f16<<<qkv_grid, 256, GSMEM5>>>(hQ, hK, hV, hWq, hWk, hWv, pq, pk, pv);

    dim3 sp_grid((NNG + TB - 1) / TB, HH);  // (64, 16)
    sparse_attn<<<sp_grid, 256>>>(idx);

    dim3 gs_grid(NSPL, HH, 2);
    global_attn_split<<<gs_grid, 256>>>();
    global_attn_combine<<<2 * HH, 64>>>();

    dim3 o_grid(DM / BN3, SS / BM3, 1);     // (4, 32, 1)
    gemm_f16<<<o_grid, 256, GSMEM5>>>(oh, oh, oh, hWo, hWo, hWo, out, out, out);
}

// round 15
// speedup vs baseline: 1.8436x; 1.1772x over previous
#include <cuda_runtime.h>
#include <cuda_fp16.h>
#include <math.h>
#include <stdint.h>

#define SS   4096
#define DM   1024
#define HH   16
#define DKK  64
#define GG   1
#define NNG  (SS - 2*GG)     // 4094
#define KSEL 32
#define SCALE 0.125f         // 1/sqrt(64)
#define NSPL 16

// Scratch (device globals — no allocation allowed)
__device__ __half g_oh[SS*DM];          // attention output, fp16 (A of out-GEMM)
__device__ __half g_qp[SS*DM];          // projected q/k/v, fp16 (GEMM epilogue)
__device__ __half g_kp[SS*DM];
__device__ __half g_vp[SS*DM];
__device__ __half g_hQ[SS*DM];          // fp16 copies of inputs
__device__ __half g_hK[SS*DM];
__device__ __half g_hV[SS*DM];
__device__ __half g_hWq[DM*DM];
__device__ __half g_hWk[DM*DM];
__device__ __half g_hWv[DM*DM];
__device__ __half g_hWo[DM*DM];
__device__ float  g_gpart[2*HH*NSPL*72];

// ---------------------------------------------------------------------------
// Fused fp32 -> fp16 convert for all 7 input buffers, one launch.
// ---------------------------------------------------------------------------
__global__ void f2h_all(const float4* __restrict__ Q,  const float4* __restrict__ K,
                        const float4* __restrict__ V,  const float4* __restrict__ Wq,
                        const float4* __restrict__ Wk, const float4* __restrict__ Wv,
                        const float4* __restrict__ Wo) {
    const int z = blockIdx.y;
    const int i = blockIdx.x * blockDim.x + threadIdx.x;
    const float4* s;
    uint2* d;
    int n4;
    switch (z) {
        case 0: s = Q;  d = (uint2*)g_hQ;  n4 = SS*DM/4; break;
        case 1: s = K;  d = (uint2*)g_hK;  n4 = SS*DM/4; break;
        case 2: s = V;  d = (uint2*)g_hV;  n4 = SS*DM/4; break;
        case 3: s = Wq; d = (uint2*)g_hWq; n4 = DM*DM/4; break;
        case 4: s = Wk; d = (uint2*)g_hWk; n4 = DM*DM/4; break;
        case 5: s = Wv; d = (uint2*)g_hWv; n4 = DM*DM/4; break;
        default: s = Wo; d = (uint2*)g_hWo; n4 = DM*DM/4; break;
    }
    if (i >= n4) return;
    float4 v = s[i];
    __half2 lo = __floats2half2_rn(v.x, v.y);
    __half2 hi = __floats2half2_rn(v.z, v.w);
    d[i] = make_uint2(*(uint32_t*)&lo, *(uint32_t*)&hi);
}

// ===========================================================================
// FP16 GEMM (R14 pipeline): CTA 128x256, BK=32 halves, 8 warps (2M x 4N),
// warp 64x64, f32 accumulate, double-buffered register-staged prefetch,
// one __syncthreads per iter. Epilogue: fp32 C (Cf) or fp16 C (Ch*, per z).
// ===========================================================================
#define BM3 128
#define BN3 256
#define A_STRIDE 80
#define A_BUF    10240
#define B_OFF    20480
#define B_BUF    16384
#define GSMEM5   53248

__device__ __forceinline__ uint32_t smem_u32(const void* p) {
    uint32_t a;
    asm("{ .reg .u64 t; cvta.to.shared.u64 t, %1; cvt.u32.u64 %0, t; }"
        : "=r"(a) : "l"(p));
    return a;
}
__device__ __forceinline__ uint32_t fpack(float a, float b) {
    __half2 h = __floats2half2_rn(a, b);
    return *reinterpret_cast<uint32_t*>(&h);
}

#define LDM_X4(r, a) \
    asm volatile("ldmatrix.sync.aligned.m8n8.x4.shared.b16 {%0,%1,%2,%3}, [%4];" \
        : "=r"((r)[0]), "=r"((r)[1]), "=r"((r)[2]), "=r"((r)[3]) : "r"(a))
#define LDM_X4T(r, a) \
    asm volatile("ldmatrix.sync.aligned.m8n8.x4.trans.shared.b16 {%0,%1,%2,%3}, [%4];" \
        : "=r"((r)[0]), "=r"((r)[1]), "=r"((r)[2]), "=r"((r)[3]) : "r"(a))

__device__ __forceinline__ void mma_f16(float& c0, float& c1, float& c2, float& c3,
                                        uint32_t a0, uint32_t a1, uint32_t a2, uint32_t a3,
                                        uint32_t b0, uint32_t b1) {
    asm volatile(
        "mma.sync.aligned.m16n8k16.row.col.f32.f16.f16.f32 "
        "{%0,%1,%2,%3}, {%4,%5,%6,%7}, {%8,%9}, {%0,%1,%2,%3};"
        : "+f"(c0), "+f"(c1), "+f"(c2), "+f"(c3)
        : "r"(a0), "r"(a1), "r"(a2), "r"(a3), "r"(b0), "r"(b1));
}

__global__ __launch_bounds__(256, 1)
void gemm_f16(const __half* __restrict__ A0, const __half* __restrict__ A1,
              const __half* __restrict__ A2, const __half* __restrict__ B0,
              const __half* __restrict__ B1, const __half* __restrict__ B2,
              float* __restrict__ Cf,
              __half* __restrict__ Ch0, __half* __restrict__ Ch1,
              __half* __restrict__ Ch2) {
    extern __shared__ char dsm[];
    const uint32_t sb = smem_u32(dsm);

    const int N = DM;
    const __half* A = (blockIdx.z == 0) ? A0 : (blockIdx.z == 1) ? A1 : A2;
    const __half* B = (blockIdx.z == 0) ? B0 : (blockIdx.z == 1) ? B1 : B2;
    __half*      Ch = (blockIdx.z == 0) ? Ch0 : (blockIdx.z == 1) ? Ch1 : Ch2;

    const int tid  = threadIdx.x;
    const int lane = tid & 31;
    const int warp = tid >> 5;
    const int wm   = warp >> 2;
    const int wn   = warp & 3;
    const int gid  = lane >> 2;
    const int qid  = lane & 3;
    const int bx = blockIdx.x;
    const int by = blockIdx.y;

    const int am  = tid >> 1;
    const int acp = tid & 1;
    const __half* Ag = A + (size_t)(by * BM3 + am) * DM + acp * 16;
    const uint32_t aoffS = am * A_STRIDE + acp * 32;
    const int br  = tid >> 3;
    const int bcb = tid & 7;
    const __half* Bg = B + (size_t)br * DM + bx * BN3 + bcb * 8;
    uint32_t boffS[4];
#pragma unroll
    for (int jj = 0; jj < 4; jj++)
        boffS[jj] = br * 512 + (8 * jj + (bcb ^ (br & 7))) * 16;

    const uint32_t aBase0 = (uint32_t)((wm * 64 + (lane & 7) + ((lane >> 3) & 1) * 8) * A_STRIDE
                                       + (lane >> 4) * 16);
    const uint32_t bBase0 = (uint32_t)(lane * 512 + wn * 128);
    const int lx = lane & 7;

    float acc[4][8][4];
#pragma unroll
    for (int mi = 0; mi < 4; mi++)
#pragma unroll
        for (int ni = 0; ni < 8; ni++)
#pragma unroll
            for (int r = 0; r < 4; r++) acc[mi][ni][r] = 0.0f;

    uint4 pa[2], pb[4];

    pa[0] = *(const uint4*)(Ag);
    pa[1] = *(const uint4*)(Ag + 8);
#pragma unroll
    for (int jj = 0; jj < 4; jj++) pb[jj] = *(const uint4*)(Bg + jj * 64);
    {
        *(uint4*)(dsm + aoffS)      = pa[0];
        *(uint4*)(dsm + aoffS + 16) = pa[1];
#pragma unroll
        for (int jj = 0; jj < 4; jj++)
            *(uint4*)(dsm + B_OFF + boffS[jj]) = pb[jj];
    }
    __syncthreads();

    const int NITER = DM / 32;
    for (int it = 0; it < NITER; it++) {
        const int cur = it & 1;

        if (it + 1 < NITER) {
            const int k0 = (it + 1) * 32;
            pa[0] = *(const uint4*)(Ag + k0);
            pa[1] = *(const uint4*)(Ag + k0 + 8);
            const __half* Bg2 = Bg + (size_t)k0 * DM;
#pragma unroll
            for (int jj = 0; jj < 4; jj++) pb[jj] = *(const uint4*)(Bg2 + jj * 64);
        }

        const uint32_t aB = sb + cur * A_BUF + aBase0;
        const uint32_t bB = sb + B_OFF + cur * B_BUF + bBase0;
        uint32_t afr[8][4];
#pragma unroll
        for (int mi = 0; mi < 4; mi++) {
            LDM_X4(afr[mi * 2 + 0], aB + mi * (16 * A_STRIDE) + 0);
            LDM_X4(afr[mi * 2 + 1], aB + mi * (16 * A_STRIDE) + 32);
        }
        uint32_t bfr[8][4];
#pragma unroll
        for (int ni = 0; ni < 8; ni++)
            LDM_X4T(bfr[ni], bB + ((ni ^ lx) << 4));

#pragma unroll
        for (int kc = 0; kc < 2; kc++)
#pragma unroll
            for (int mi = 0; mi < 4; mi++)
#pragma unroll
                for (int ni = 0; ni < 8; ni++)
                    mma_f16(acc[mi][ni][0], acc[mi][ni][1], acc[mi][ni][2], acc[mi][ni][3],
                            afr[mi * 2 + kc][0], afr[mi * 2 + kc][1],
                            afr[mi * 2 + kc][2], afr[mi * 2 + kc][3],
                            bfr[ni][2 * kc], bfr[ni][2 * kc + 1]);

        if (it + 1 < NITER) {
            const int nxt = (it + 1) & 1;
            char* ab = dsm + nxt * A_BUF + aoffS;
            *(uint4*)(ab)      = pa[0];
            *(uint4*)(ab + 16) = pa[1];
            char* bb = dsm + B_OFF + nxt * B_BUF;
#pragma unroll
            for (int jj = 0; jj < 4; jj++)
                *(uint4*)(bb + boffS[jj]) = pb[jj];
        }
        __syncthreads();
    }

    // epilogue: fp32 C (out projection) or fp16 C (q/k/v projections)
    if (Cf != nullptr) {
#pragma unroll
        for (int mi = 0; mi < 4; mi++) {
            const int row = by * BM3 + wm * 64 + mi * 16 + gid;
#pragma unroll
            for (int ni = 0; ni < 8; ni++) {
                const int col = bx * BN3 + wn * 64 + ni * 8 + 2 * qid;
                *(float2*)(Cf + (size_t)row * N + col) =
                    make_float2(acc[mi][ni][0], acc[mi][ni][1]);
                *(float2*)(Cf + (size_t)(row + 8) * N + col) =
                    make_float2(acc[mi][ni][2], acc[mi][ni][3]);
            }
        }
    } else {
#pragma unroll
        for (int mi = 0; mi < 4; mi++) {
            const int row = by * BM3 + wm * 64 + mi * 16 + gid;
#pragma unroll
            for (int ni = 0; ni < 8; ni++) {
                const int col = bx * BN3 + wn * 64 + ni * 8 + 2 * qid;
                *(uint32_t*)(Ch + (size_t)row * N + col) =
                    fpack(acc[mi][ni][0], acc[mi][ni][1]);
                *(uint32_t*)(Ch + (size_t)(row + 8) * N + col) =
                    fpack(acc[mi][ni][2], acc[mi][ni][3]);
            }
        }
    }
}

// ---------------------------------------------------------------------------
// Sparse attention (fp16 K/V/Q): CTA = 64 tokens x 1 head, half2 smem cache.
// Lane owns output dims (2*lane, 2*lane+1). idx int64/int32 sniffed inline.
// ---------------------------------------------------------------------------
#define TB     64
#define CROWS  96
#define CSLOTS 97
#define CSTR2  40      // half2 per cached row (32 data + 8 pad)

__global__ __launch_bounds__(256)
void sparse_attn(const void* __restrict__ idxraw) {
    __shared__ uint32_t Kc[CSLOTS * CSTR2];   // half2
    __shared__ uint32_t Vc[CSLOTS * CSTR2];
    __shared__ float2 qsm[8][32];

    const int b    = blockIdx.x;
    const int h    = blockIdx.y;
    const int tid  = threadIdx.x;
    const int lane = tid & 31;
    const int w    = tid >> 5;

    const int* p32 = (const int*)idxraw;
    const bool is64 = (p32[1] == 0);

    int rowbase = b * TB - 10;
    if (rowbase < 0) rowbase = 0;
    if (rowbase > SS - CROWS) rowbase = SS - CROWS;

    // cache fill: 97 rows x 8 uint4 (16B) per tensor
    for (int i = tid; i < CSLOTS * 8; i += 256) {
        const int r = i >> 3;
        const int c = i & 7;
        const int src = (r < CROWS) ? (rowbase + r) : 0;
        const uint4 kv = *(const uint4*)(g_kp + (size_t)src * DM + h * DKK + c * 8);
        const uint4 vv = *(const uint4*)(g_vp + (size_t)src * DM + h * DKK + c * 8);
        *(uint4*)(&Kc[r * CSTR2 + c * 4]) = kv;
        *(uint4*)(&Vc[r * CSTR2 + c * 4]) = vv;
    }
    __syncthreads();

    for (int i = 0; i < 8; i++) {
        const int t = b * TB + w * 8 + i;
        if (t >= NNG) break;

        __syncwarp();
        {
            const __half2 qh = ((const __half2*)(g_qp + (size_t)(t + GG) * DM + h * DKK))[lane];
            qsm[w][lane] = __half22float2(qh);
        }
        __syncwarp();

        const int kidx = is64 ? (int)((const long long*)idxraw)[t * KSEL + lane]
                              : p32[t * KSEL + lane];
        int slot = kidx - rowbase;
        if (kidx == 0) slot = CROWS;
        else if (slot < 0 || slot >= CROWS) slot = -1;

        float dot = 0.0f;
        if (slot >= 0) {
            const uint32_t* kr = &Kc[slot * CSTR2];
            const int rot = slot & 31;
#pragma unroll
            for (int pp = 0; pp < 32; pp++) {
                const int p = (pp + rot) & 31;
                const float2 kv = __half22float2(*(const __half2*)&kr[p]);
                const float2 qv = qsm[w][p];
                dot += kv.x * qv.x + kv.y * qv.y;
            }
        } else {
            const __half2* kr = (const __half2*)(g_kp + (size_t)kidx * DM + h * DKK);
#pragma unroll
            for (int pp = 0; pp < 32; pp++) {
                const int p = (pp + lane) & 31;
                const float2 kv = __half22float2(kr[p]);
                const float2 qv = qsm[w][p];
                dot += kv.x * qv.x + kv.y * qv.y;
            }
        }
        const float lg = dot * SCALE;

        float m = lg;
#pragma unroll
        for (int o = 16; o; o >>= 1) m = fmaxf(m, __shfl_xor_sync(0xffffffffu, m, o));
        const float e = __expf(lg - m);
        float sum = e;
#pragma unroll
        for (int o = 16; o; o >>= 1) sum += __shfl_xor_sync(0xffffffffu, sum, o);
        const float prob = e / sum;

        // PV: lane owns dims (2*lane, 2*lane+1)
        float acc0 = 0.0f, acc1 = 0.0f;
#pragma unroll
        for (int j = 0; j < 32; j++) {
            const float pj = __shfl_sync(0xffffffffu, prob, j);
            const int   sj = __shfl_sync(0xffffffffu, slot, j);
            const int   kj = __shfl_sync(0xffffffffu, kidx, j);
            float2 vv;
            if (sj >= 0) {
                vv = __half22float2(*(const __half2*)&Vc[sj * CSTR2 + lane]);
            } else {
                vv = __half22float2(((const __half2*)(g_vp + (size_t)kj * DM + h * DKK))[lane]);
            }
            acc0 = fmaf(pj, vv.x, acc0);
            acc1 = fmaf(pj, vv.y, acc1);
        }
        ((__half2*)(g_oh + (size_t)(t + GG) * DM + h * DKK))[lane] =
            __floats2half2_rn(acc0, acc1);
    }
}

// ---------------------------------------------------------------------------
// Global attention, split-K x16 (fp16 K/V/Q): grid (16, 16, 2), 256 keys/blk.
// ---------------------------------------------------------------------------
__global__ __launch_bounds__(256)
void global_attn_split() {
    __shared__ float lg[256];
    __shared__ float red[256];
    __shared__ float ored[4][DKK];
    __shared__ float2 qs2[32];

    const int spl = blockIdx.x;
    const int h   = blockIdx.y;
    const int gi  = blockIdx.z;
    const int srow = gi ? (SS - 1) : 0;
    const int tid = threadIdx.x;
    const int n0  = spl * 256;

    if (tid < 32)
        qs2[tid] = __half22float2(((const __half2*)(g_qp + (size_t)srow * DM + h * DKK))[tid]);
    __syncthreads();

    {
        const int n = n0 + tid;
        const __half2* kr = (const __half2*)(g_kp + (size_t)n * DM + h * DKK);
        float dot = 0.0f;
#pragma unroll
        for (int i = 0; i < 32; i++) {
            const float2 kv = __half22float2(kr[i]);
            const float2 qv = qs2[i];
            dot = fmaf(kv.x, qv.x, fmaf(kv.y, qv.y, dot));
        }
        lg[tid] = dot * SCALE;
    }
    red[tid] = lg[tid]; __syncthreads();
    for (int st = 128; st; st >>= 1) {
        if (tid < st) red[tid] = fmaxf(red[tid], red[tid + st]);
        __syncthreads();
    }
    const float m = red[0];
    __syncthreads();

    const float e = __expf(lg[tid] - m);
    lg[tid] = e;
    red[tid] = e; __syncthreads();
    for (int st = 128; st; st >>= 1) {
        if (tid < st) red[tid] += red[tid + st];
        __syncthreads();
    }
    const float s = red[0];
    __syncthreads();

    const int d = tid & 63;
    const int c = tid >> 6;
    float acc = 0.0f;
    const __half* vb = g_vp + h * DKK + d;
    const int na = c * 64, nb = na + 64;
    for (int nl = na; nl < nb; nl++)
        acc = fmaf(lg[nl], __half2float(vb[(size_t)(n0 + nl) * DM]), acc);
    ored[c][d] = acc;
    __syncthreads();

    const int base = ((gi * HH + h) * NSPL + spl) * 72;
    if (tid < DKK)
        g_gpart[base + tid] = ored[0][tid] + ored[1][tid] + ored[2][tid] + ored[3][tid];
    else if (tid == 64) g_gpart[base + 64] = m;
    else if (tid == 65) g_gpart[base + 65] = s;
}

__global__ __launch_bounds__(64)
void global_attn_combine() {
    const int blk = blockIdx.x;
    const int d   = threadIdx.x;
    const int gi  = blk >> 4;
    const int h   = blk & 15;
    const int srow = gi ? (SS - 1) : 0;

    float M = -1e30f;
#pragma unroll
    for (int i = 0; i < NSPL; i++)
        M = fmaxf(M, g_gpart[(blk * NSPL + i) * 72 + 64]);
    float S = 0.0f, acc = 0.0f;
#pragma unroll
    for (int i = 0; i < NSPL; i++) {
        const int base = (blk * NSPL + i) * 72;
        const float wgt = __expf(g_gpart[base + 64] - M);
        S   += g_gpart[base + 65] * wgt;
        acc += g_gpart[base + d] * wgt;
    }
    g_oh[(size_t)srow * DM + h * DKK + d] = __float2half(acc / S);
}

// ---------------------------------------------------------------------------
extern "C" void kernel_launch(void* const* d_in, const int* in_sizes, int n_in,
                              void* d_out, int out_size) {
    const float* Q  = (const float*)d_in[0];
    const float* Kk = (const float*)d_in[1];
    const float* V  = (const float*)d_in[2];
    const float* Wq = (const float*)d_in[3];
    const float* Wk = (const float*)d_in[4];
    const float* Wv = (const float*)d_in[5];
    const float* Wo = (const float*)d_in[6];
    const void*  idx = (const void*)d_in[7];
    float* out = (float*)d_out;

    __half *hQ, *hK, *hV, *hWq, *hWk, *hWv, *hWo, *oh, *qp, *kp, *vp;
    cudaGetSymbolAddress((void**)&hQ,  g_hQ);
    cudaGetSymbolAddress((void**)&hK,  g_hK);
    cudaGetSymbolAddress((void**)&hV,  g_hV);
    cudaGetSymbolAddress((void**)&hWq, g_hWq);
    cudaGetSymbolAddress((void**)&hWk, g_hWk);
    cudaGetSymbolAddress((void**)&hWv, g_hWv);
    cudaGetSymbolAddress((void**)&hWo, g_hWo);
    cudaGetSymbolAddress((void**)&oh,  g_oh);
    cudaGetSymbolAddress((void**)&qp,  g_qp);
    cudaGetSymbolAddress((void**)&kp,  g_kp);
    cudaGetSymbolAddress((void**)&vp,  g_vp);

    cudaFuncSetAttribute(gemm_f16, cudaFuncAttributeMaxDynamicSharedMemorySize, GSMEM5);

    // fused fp32 -> fp16 conversion of all inputs, single launch
    dim3 cg(SS * DM / 4 / 256, 7);
    f2h_all<<<cg, 256>>>((const float4*)Q,  (const float4*)Kk, (const float4*)V,
                         (const float4*)Wq, (const float4*)Wk, (const float4*)Wv,
                         (const float4*)Wo);

    // QKV projections -> fp16 outputs
    dim3 qkv_grid(DM / BN3, SS / BM3, 3);   // (4, 32, 3)
    gemm_f16<<<qkv_grid, 256, GSMEM5>>>(hQ, hK, hV, hWq, hWk, hWv,
                                        nullptr, qp, kp, vp);

    dim3 sp_grid((NNG + TB - 1) / TB, HH);  // (64, 16)
    sparse_attn<<<sp_grid, 256>>>(idx);

    dim3 gs_grid(NSPL, HH, 2);
    global_attn_split<<<gs_grid, 256>>>();
    global_attn_combine<<<2 * HH, 64>>>();

    // out projection -> fp32 output
    dim3 o_grid(DM / BN3, SS / BM3, 1);     // (4, 32, 1)
    gemm_f16<<<o_grid, 256, GSMEM5>>>(oh, oh, oh, hWo, hWo, hWo,
                                      out, nullptr, nullptr, nullptr);
}

// round 16
// speedup vs baseline: 1.8536x; 1.0054x over previous
#include <cuda_runtime.h>
#include <cuda_fp16.h>
#include <math.h>
#include <stdint.h>

#define SS   4096
#define DM   1024
#define HH   16
#define DKK  64
#define GG   1
#define NNG  (SS - 2*GG)     // 4094
#define KSEL 32
#define SCALE 0.125f         // 1/sqrt(64)
#define NSPL 16

// Scratch (device globals — no allocation allowed)
__device__ __half g_oh[SS*DM];          // attention output, fp16 (A of out-GEMM)
__device__ __half g_qp[SS*DM];          // projected q/k/v, fp16
__device__ __half g_kp[SS*DM];
__device__ __half g_vp[SS*DM];
__device__ __half g_hQ[SS*DM];          // fp16 copies of inputs
__device__ __half g_hK[SS*DM];
__device__ __half g_hV[SS*DM];
__device__ __half g_hWq[DM*DM];
__device__ __half g_hWk[DM*DM];
__device__ __half g_hWv[DM*DM];
__device__ __half g_hWo[DM*DM];
__device__ float  g_gpart[2*HH*NSPL*72];

// ---------------------------------------------------------------------------
// Fused fp32 -> fp16 convert for all 7 input buffers, one launch.
// ---------------------------------------------------------------------------
__global__ void f2h_all(const float4* __restrict__ Q,  const float4* __restrict__ K,
                        const float4* __restrict__ V,  const float4* __restrict__ Wq,
                        const float4* __restrict__ Wk, const float4* __restrict__ Wv,
                        const float4* __restrict__ Wo) {
    const int z = blockIdx.y;
    const int i = blockIdx.x * blockDim.x + threadIdx.x;
    const float4* s;
    uint2* d;
    int n4;
    switch (z) {
        case 0: s = Q;  d = (uint2*)g_hQ;  n4 = SS*DM/4; break;
        case 1: s = K;  d = (uint2*)g_hK;  n4 = SS*DM/4; break;
        case 2: s = V;  d = (uint2*)g_hV;  n4 = SS*DM/4; break;
        case 3: s = Wq; d = (uint2*)g_hWq; n4 = DM*DM/4; break;
        case 4: s = Wk; d = (uint2*)g_hWk; n4 = DM*DM/4; break;
        case 5: s = Wv; d = (uint2*)g_hWv; n4 = DM*DM/4; break;
        default: s = Wo; d = (uint2*)g_hWo; n4 = DM*DM/4; break;
    }
    if (i >= n4) return;
    float4 v = s[i];
    __half2 lo = __floats2half2_rn(v.x, v.y);
    __half2 hi = __floats2half2_rn(v.z, v.w);
    d[i] = make_uint2(*(uint32_t*)&lo, *(uint32_t*)&hi);
}

// ===========================================================================
// FP16 GEMM v6: CTA 128x256, BK=32 halves, 512 threads = 16 warps (4M x 4N),
// warp 32x64, f32 accumulate. Same smem layouts as R14 (proven):
//  A smem: [128 m][32 k-halves], row stride 80B (no swizzle).
//  B smem: [32 k][256 n-halves], row stride 512B, chunk swizzle
//          p = (c & 24) | ((c&7) ^ (r&7)); ldmatrix.x4.trans.
// Double-buffered, register-staged prefetch, one __syncthreads per iter.
// ===========================================================================
#define BM3 128
#define BN3 256
#define A_STRIDE 80
#define A_BUF    10240
#define B_OFF    20480
#define B_BUF    16384
#define GSMEM5   53248

__device__ __forceinline__ uint32_t smem_u32(const void* p) {
    uint32_t a;
    asm("{ .reg .u64 t; cvta.to.shared.u64 t, %1; cvt.u32.u64 %0, t; }"
        : "=r"(a) : "l"(p));
    return a;
}
__device__ __forceinline__ uint32_t fpack(float a, float b) {
    __half2 h = __floats2half2_rn(a, b);
    return *reinterpret_cast<uint32_t*>(&h);
}

#define LDM_X4(r, a) \
    asm volatile("ldmatrix.sync.aligned.m8n8.x4.shared.b16 {%0,%1,%2,%3}, [%4];" \
        : "=r"((r)[0]), "=r"((r)[1]), "=r"((r)[2]), "=r"((r)[3]) : "r"(a))
#define LDM_X4T(r, a) \
    asm volatile("ldmatrix.sync.aligned.m8n8.x4.trans.shared.b16 {%0,%1,%2,%3}, [%4];" \
        : "=r"((r)[0]), "=r"((r)[1]), "=r"((r)[2]), "=r"((r)[3]) : "r"(a))

__device__ __forceinline__ void mma_f16(float& c0, float& c1, float& c2, float& c3,
                                        uint32_t a0, uint32_t a1, uint32_t a2, uint32_t a3,
                                        uint32_t b0, uint32_t b1) {
    asm volatile(
        "mma.sync.aligned.m16n8k16.row.col.f32.f16.f16.f32 "
        "{%0,%1,%2,%3}, {%4,%5,%6,%7}, {%8,%9}, {%0,%1,%2,%3};"
        : "+f"(c0), "+f"(c1), "+f"(c2), "+f"(c3)
        : "r"(a0), "r"(a1), "r"(a2), "r"(a3), "r"(b0), "r"(b1));
}

__global__ __launch_bounds__(512, 1)
void gemm_f16(const __half* __restrict__ A0, const __half* __restrict__ A1,
              const __half* __restrict__ A2, const __half* __restrict__ B0,
              const __half* __restrict__ B1, const __half* __restrict__ B2,
              float* __restrict__ Cf,
              __half* __restrict__ Ch0, __half* __restrict__ Ch1,
              __half* __restrict__ Ch2) {
    extern __shared__ char dsm[];
    const uint32_t sb = smem_u32(dsm);

    const int N = DM;
    const __half* A = (blockIdx.z == 0) ? A0 : (blockIdx.z == 1) ? A1 : A2;
    const __half* B = (blockIdx.z == 0) ? B0 : (blockIdx.z == 1) ? B1 : B2;
    __half*      Ch = (blockIdx.z == 0) ? Ch0 : (blockIdx.z == 1) ? Ch1 : Ch2;

    const int tid  = threadIdx.x;
    const int lane = tid & 31;
    const int warp = tid >> 5;
    const int wm   = warp >> 2;       // 0..3 -> M (32 rows each)
    const int wn   = warp & 3;        // 0..3 -> N (64 cols each)
    const int gid  = lane >> 2;
    const int qid  = lane & 3;
    const int bx = blockIdx.x;
    const int by = blockIdx.y;

    // --- fill mappings (512 threads) ---
    // A: thread -> row am (0..127), chunk acp (0..3, 16B each): 1 LDG + 1 STS
    const int am  = tid >> 2;
    const int acp = tid & 3;
    const __half* Ag = A + (size_t)(by * BM3 + am) * DM + acp * 8;
    const uint32_t aoffS = am * A_STRIDE + acp * 16;
    // B: thread -> k-row br (0..31), chunks bcb and bcb+16: 2 LDG + 2 STS
    const int br  = tid >> 4;
    const int bcb = tid & 15;
    const __half* Bg = B + (size_t)br * DM + bx * BN3 + bcb * 8;
    uint32_t boffS[2];
#pragma unroll
    for (int jj = 0; jj < 2; jj++) {
        const int c = bcb + jj * 16;
        boffS[jj] = br * 512 + (((c & 24) | ((c & 7) ^ (br & 7))) * 16);
    }

    // --- ldmatrix lane bases ---
    const uint32_t aBase0 = (uint32_t)((wm * 32 + (lane & 7) + ((lane >> 3) & 1) * 8) * A_STRIDE
                                       + (lane >> 4) * 16);
    const uint32_t bBase0 = (uint32_t)(lane * 512 + wn * 128);
    const int lx = lane & 7;

    float acc[2][8][4];
#pragma unroll
    for (int mi = 0; mi < 2; mi++)
#pragma unroll
        for (int ni = 0; ni < 8; ni++)
#pragma unroll
            for (int r = 0; r < 4; r++) acc[mi][ni][r] = 0.0f;

    uint4 pa, pb[2];

    // ---- prologue: stage 0 ----
    pa = *(const uint4*)(Ag);
    pb[0] = *(const uint4*)(Bg);
    pb[1] = *(const uint4*)(Bg + 128);
    *(uint4*)(dsm + aoffS) = pa;
    *(uint4*)(dsm + B_OFF + boffS[0]) = pb[0];
    *(uint4*)(dsm + B_OFF + boffS[1]) = pb[1];
    __syncthreads();

    const int NITER = DM / 32;
    for (int it = 0; it < NITER; it++) {
        const int cur = it & 1;

        if (it + 1 < NITER) {
            const int k0 = (it + 1) * 32;
            pa = *(const uint4*)(Ag + k0);
            const __half* Bg2 = Bg + (size_t)k0 * DM;
            pb[0] = *(const uint4*)(Bg2);
            pb[1] = *(const uint4*)(Bg2 + 128);
        }

        const uint32_t aB = sb + cur * A_BUF + aBase0;
        const uint32_t bB = sb + B_OFF + cur * B_BUF + bBase0;
        uint32_t afr[4][4];    // [mi*2+kc]
#pragma unroll
        for (int mi = 0; mi < 2; mi++) {
            LDM_X4(afr[mi * 2 + 0], aB + mi * (16 * A_STRIDE) + 0);
            LDM_X4(afr[mi * 2 + 1], aB + mi * (16 * A_STRIDE) + 32);
        }

        // ni processed in two halves of 4 to bound register pressure
#pragma unroll
        for (int nh = 0; nh < 2; nh++) {
            uint32_t bfr[4][4];
#pragma unroll
            for (int nq = 0; nq < 4; nq++)
                LDM_X4T(bfr[nq], bB + (((nh * 4 + nq) ^ lx) << 4));
#pragma unroll
            for (int kc = 0; kc < 2; kc++)
#pragma unroll
                for (int mi = 0; mi < 2; mi++)
#pragma unroll
                    for (int nq = 0; nq < 4; nq++)
                        mma_f16(acc[mi][nh * 4 + nq][0], acc[mi][nh * 4 + nq][1],
                                acc[mi][nh * 4 + nq][2], acc[mi][nh * 4 + nq][3],
                                afr[mi * 2 + kc][0], afr[mi * 2 + kc][1],
                                afr[mi * 2 + kc][2], afr[mi * 2 + kc][3],
                                bfr[nq][2 * kc], bfr[nq][2 * kc + 1]);
        }

        if (it + 1 < NITER) {
            const int nxt = (it + 1) & 1;
            *(uint4*)(dsm + nxt * A_BUF + aoffS) = pa;
            char* bb = dsm + B_OFF + nxt * B_BUF;
            *(uint4*)(bb + boffS[0]) = pb[0];
            *(uint4*)(bb + boffS[1]) = pb[1];
        }
        __syncthreads();
    }

    // epilogue
    if (Cf != nullptr) {
#pragma unroll
        for (int mi = 0; mi < 2; mi++) {
            const int row = by * BM3 + wm * 32 + mi * 16 + gid;
#pragma unroll
            for (int ni = 0; ni < 8; ni++) {
                const int col = bx * BN3 + wn * 64 + ni * 8 + 2 * qid;
                *(float2*)(Cf + (size_t)row * N + col) =
                    make_float2(acc[mi][ni][0], acc[mi][ni][1]);
                *(float2*)(Cf + (size_t)(row + 8) * N + col) =
                    make_float2(acc[mi][ni][2], acc[mi][ni][3]);
            }
        }
    } else {
#pragma unroll
        for (int mi = 0; mi < 2; mi++) {
            const int row = by * BM3 + wm * 32 + mi * 16 + gid;
#pragma unroll
            for (int ni = 0; ni < 8; ni++) {
                const int col = bx * BN3 + wn * 64 + ni * 8 + 2 * qid;
                *(uint32_t*)(Ch + (size_t)row * N + col) =
                    fpack(acc[mi][ni][0], acc[mi][ni][1]);
                *(uint32_t*)(Ch + (size_t)(row + 8) * N + col) =
                    fpack(acc[mi][ni][2], acc[mi][ni][3]);
            }
        }
    }
}

// ===========================================================================
// Fused attention kernel: blocks [0, 1024) = sparse (64 tokens x 1 head),
// blocks [1024, 1536) = global split-K partials. 256 threads, smem union.
// ===========================================================================
#define TB     64
#define CROWS  96
#define CSLOTS 97
#define CSTR2  40                       // half2 slots per cached row
#define SPAR_SMEM (CSLOTS*CSTR2*4*2 + 8*32*8)   // 33088

__global__ __launch_bounds__(256)
void attn_fused(const void* __restrict__ idxraw) {
    __shared__ __align__(16) char smb[SPAR_SMEM];

    const int tid  = threadIdx.x;

    if (blockIdx.x < 1024) {
        // ----------------- sparse attention -----------------
        uint32_t* Kc = (uint32_t*)smb;                       // 97*40 half2
        uint32_t* Vc = (uint32_t*)(smb + CSLOTS*CSTR2*4);
        float2  (*qsm)[32] = (float2(*)[32])(smb + CSLOTS*CSTR2*8);

        const int b    = blockIdx.x >> 4;
        const int h    = blockIdx.x & 15;
        const int lane = tid & 31;
        const int w    = tid >> 5;

        const int* p32 = (const int*)idxraw;
        const bool is64 = (p32[1] == 0);

        int rowbase = b * TB - 10;
        if (rowbase < 0) rowbase = 0;
        if (rowbase > SS - CROWS) rowbase = SS - CROWS;

        for (int i = tid; i < CSLOTS * 8; i += 256) {
            const int r = i >> 3;
            const int c = i & 7;
            const int src = (r < CROWS) ? (rowbase + r) : 0;
            const uint4 kv = *(const uint4*)(g_kp + (size_t)src * DM + h * DKK + c * 8);
            const uint4 vv = *(const uint4*)(g_vp + (size_t)src * DM + h * DKK + c * 8);
            *(uint4*)(&Kc[r * CSTR2 + c * 4]) = kv;
            *(uint4*)(&Vc[r * CSTR2 + c * 4]) = vv;
        }
        __syncthreads();

        for (int i = 0; i < 8; i++) {
            const int t = b * TB + w * 8 + i;
            if (t >= NNG) break;

            __syncwarp();
            {
                const __half2 qh = ((const __half2*)(g_qp + (size_t)(t + GG) * DM + h * DKK))[lane];
                qsm[w][lane] = __half22float2(qh);
            }
            __syncwarp();

            const int kidx = is64 ? (int)((const long long*)idxraw)[t * KSEL + lane]
                                  : p32[t * KSEL + lane];
            int slot = kidx - rowbase;
            if (kidx == 0) slot = CROWS;
            else if (slot < 0 || slot >= CROWS) slot = -1;

            float dot = 0.0f;
            if (slot >= 0) {
                const uint32_t* kr = &Kc[slot * CSTR2];
                const int rot = slot & 31;
#pragma unroll
                for (int pp = 0; pp < 32; pp++) {
                    const int p = (pp + rot) & 31;
                    const float2 kv = __half22float2(*(const __half2*)&kr[p]);
                    const float2 qv = qsm[w][p];
                    dot += kv.x * qv.x + kv.y * qv.y;
                }
            } else {
                const __half2* kr = (const __half2*)(g_kp + (size_t)kidx * DM + h * DKK);
#pragma unroll
                for (int pp = 0; pp < 32; pp++) {
                    const int p = (pp + lane) & 31;
                    const float2 kv = __half22float2(kr[p]);
                    const float2 qv = qsm[w][p];
                    dot += kv.x * qv.x + kv.y * qv.y;
                }
            }
            const float lg = dot * SCALE;

            float m = lg;
#pragma unroll
            for (int o = 16; o; o >>= 1) m = fmaxf(m, __shfl_xor_sync(0xffffffffu, m, o));
            const float e = __expf(lg - m);
            float sum = e;
#pragma unroll
            for (int o = 16; o; o >>= 1) sum += __shfl_xor_sync(0xffffffffu, sum, o);
            const float prob = e / sum;

            float acc0 = 0.0f, acc1 = 0.0f;
#pragma unroll
            for (int j = 0; j < 32; j++) {
                const float pj = __shfl_sync(0xffffffffu, prob, j);
                const int   sj = __shfl_sync(0xffffffffu, slot, j);
                const int   kj = __shfl_sync(0xffffffffu, kidx, j);
                float2 vv;
                if (sj >= 0) {
                    vv = __half22float2(*(const __half2*)&Vc[sj * CSTR2 + lane]);
                } else {
                    vv = __half22float2(((const __half2*)(g_vp + (size_t)kj * DM + h * DKK))[lane]);
                }
                acc0 = fmaf(pj, vv.x, acc0);
                acc1 = fmaf(pj, vv.y, acc1);
            }
            ((__half2*)(g_oh + (size_t)(t + GG) * DM + h * DKK))[lane] =
                __floats2half2_rn(acc0, acc1);
        }
    } else {
        // ----------------- global attention split -----------------
        float*  lg   = (float*)smb;                 // 256
        float*  red  = (float*)(smb + 1024);        // 256
        float2* ored = (float2*)(smb + 2048);       // 8*32
        float2* qs2  = (float2*)(smb + 4096);       // 32

        const int r3  = blockIdx.x - 1024;
        const int spl = r3 & 15;
        const int h   = (r3 >> 4) & 15;
        const int gi  = r3 >> 8;
        const int srow = gi ? (SS - 1) : 0;
        const int n0  = spl * 256;

        if (tid < 32)
            qs2[tid] = __half22float2(((const __half2*)(g_qp + (size_t)srow * DM + h * DKK))[tid]);
        __syncthreads();

        {
            const int n = n0 + tid;
            const __half2* kr = (const __half2*)(g_kp + (size_t)n * DM + h * DKK);
            float dot = 0.0f;
#pragma unroll
            for (int i = 0; i < 32; i++) {
                const float2 kv = __half22float2(kr[i]);
                const float2 qv = qs2[i];
                dot = fmaf(kv.x, qv.x, fmaf(kv.y, qv.y, dot));
            }
            lg[tid] = dot * SCALE;
        }
        red[tid] = lg[tid]; __syncthreads();
        for (int st = 128; st; st >>= 1) {
            if (tid < st) red[tid] = fmaxf(red[tid], red[tid + st]);
            __syncthreads();
        }
        const float m = red[0];
        __syncthreads();

        const float e = __expf(lg[tid] - m);
        lg[tid] = e;
        red[tid] = e; __syncthreads();
        for (int st = 128; st; st >>= 1) {
            if (tid < st) red[tid] += red[tid + st];
            __syncthreads();
        }
        const float s = red[0];
        __syncthreads();

        // PV: thread = (chunk c of 32 keys, half2 dim d2); coalesced 4B loads
        const int d2 = tid & 31;
        const int c  = tid >> 5;
        float a0 = 0.0f, a1 = 0.0f;
        const int na = c * 32, nb = na + 32;
        for (int nl = na; nl < nb; nl++) {
            const float p = lg[nl];
            const float2 vv = __half22float2(
                ((const __half2*)(g_vp + (size_t)(n0 + nl) * DM + h * DKK))[d2]);
            a0 = fmaf(p, vv.x, a0);
            a1 = fmaf(p, vv.y, a1);
        }
        ored[c * 32 + d2] = make_float2(a0, a1);
        __syncthreads();

        const int base = ((gi * HH + h) * NSPL + spl) * 72;
        if (tid < DKK) {
            const int dh = tid >> 1;
            float acc = 0.0f;
#pragma unroll
            for (int cc = 0; cc < 8; cc++) {
                const float2 t2 = ored[cc * 32 + dh];
                acc += (tid & 1) ? t2.y : t2.x;
            }
            g_gpart[base + tid] = acc;
        } else if (tid == 64) g_gpart[base + 64] = m;
        else if (tid == 65) g_gpart[base + 65] = s;
    }
}

__global__ __launch_bounds__(64)
void global_attn_combine() {
    const int blk = blockIdx.x;
    const int d   = threadIdx.x;
    const int gi  = blk >> 4;
    const int h   = blk & 15;
    const int srow = gi ? (SS - 1) : 0;

    float M = -1e30f;
#pragma unroll
    for (int i = 0; i < NSPL; i++)
        M = fmaxf(M, g_gpart[(blk * NSPL + i) * 72 + 64]);
    float S = 0.0f, acc = 0.0f;
#pragma unroll
    for (int i = 0; i < NSPL; i++) {
        const int base = (blk * NSPL + i) * 72;
        const float wgt = __expf(g_gpart[base + 64] - M);
        S   += g_gpart[base + 65] * wgt;
        acc += g_gpart[base + d] * wgt;
    }
    g_oh[(size_t)srow * DM + h * DKK + d] = __float2half(acc / S);
}

// ---------------------------------------------------------------------------
extern "C" void kernel_launch(void* const* d_in, const int* in_sizes, int n_in,
                              void* d_out, int out_size) {
    const float* Q  = (const float*)d_in[0];
    const float* Kk = (const float*)d_in[1];
    const float* V  = (const float*)d_in[2];
    const float* Wq = (const float*)d_in[3];
    const float* Wk = (const float*)d_in[4];
    const float* Wv = (const float*)d_in[5];
    const float* Wo = (const float*)d_in[6];
    const void*  idx = (const void*)d_in[7];
    float* out = (float*)d_out;

    __half *hQ, *hK, *hV, *hWq, *hWk, *hWv, *hWo, *oh, *qp, *kp, *vp;
    cudaGetSymbolAddress((void**)&hQ,  g_hQ);
    cudaGetSymbolAddress((void**)&hK,  g_hK);
    cudaGetSymbolAddress((void**)&hV,  g_hV);
    cudaGetSymbolAddress((void**)&hWq, g_hWq);
    cudaGetSymbolAddress((void**)&hWk, g_hWk);
    cudaGetSymbolAddress((void**)&hWv, g_hWv);
    cudaGetSymbolAddress((void**)&hWo, g_hWo);
    cudaGetSymbolAddress((void**)&oh,  g_oh);
    cudaGetSymbolAddress((void**)&qp,  g_qp);
    cudaGetSymbolAddress((void**)&kp,  g_kp);
    cudaGetSymbolAddress((void**)&vp,  g_vp);

    cudaFuncSetAttribute(gemm_f16, cudaFuncAttributeMaxDynamicSharedMemorySize, GSMEM5);

    dim3 cg(SS * DM / 4 / 256, 7);
    f2h_all<<<cg, 256>>>((const float4*)Q,  (const float4*)Kk, (const float4*)V,
                         (const float4*)Wq, (const float4*)Wk, (const float4*)Wv,
                         (const float4*)Wo);

    dim3 qkv_grid(DM / BN3, SS / BM3, 3);   // (4, 32, 3)
    gemm_f16<<<qkv_grid, 512, GSMEM5>>>(hQ, hK, hV, hWq, hWk, hWv,
                                        nullptr, qp, kp, vp);

    attn_fused<<<1536, 256>>>(idx);
    global_attn_combine<<<2 * HH, 64>>>();

    dim3 o_grid(DM / BN3, SS / BM3, 1);     // (4, 32, 1)
    gemm_f16<<<o_grid, 512, GSMEM5>>>(oh, oh, oh, hWo, hWo, hWo,
                                      out, nullptr, nullptr, nullptr);
}